// round 2
// baseline (speedup 1.0000x reference)
#include <cuda_runtime.h>

// Problem constants: T=1024, B=64, I=512, H=512, 3H=1536
#define NCTA 128   // persistent recurrent kernel grid (<= 148 SMs -> all co-resident)

// ---------------- device-global scratch (no allocation allowed) ----------------
__device__ float g_gx[100663296];          // [1024*64, 1536] input-side gate pre-activations
__device__ float g_h[2][32768];            // ping-pong hidden state [64, 512]
__device__ unsigned int g_bar_cnt = 0;
__device__ volatile unsigned int g_bar_gen = 0;

// ---------------- f32x2 packed-math helpers (Blackwell, PTX-only path) ----------
__device__ __forceinline__ void ffma2(unsigned long long &acc, unsigned long long a,
                                      unsigned long long b) {
    asm("fma.rn.f32x2 %0, %1, %2, %0;" : "+l"(acc) : "l"(a), "l"(b));
}
__device__ __forceinline__ unsigned long long dup2(float a) {
    unsigned long long r; asm("mov.b64 %0, {%1, %1};" : "=l"(r) : "f"(a)); return r;
}
__device__ __forceinline__ unsigned long long pack2(float lo, float hi) {
    unsigned long long r; asm("mov.b64 %0, {%1, %2};" : "=l"(r) : "f"(lo), "f"(hi)); return r;
}
__device__ __forceinline__ float sum2(unsigned long long v) {
    float lo, hi; asm("mov.b64 {%0, %1}, %2;" : "=f"(lo), "=f"(hi) : "l"(v)); return lo + hi;
}
__device__ __forceinline__ float2 unpack2(unsigned long long v) {
    float2 f; asm("mov.b64 {%0, %1}, %2;" : "=f"(f.x), "=f"(f.y) : "l"(v)); return f;
}

// ---------------- software grid barrier (all NCTA CTAs resident) ----------------
__device__ __forceinline__ void grid_sync() {
    __threadfence();
    __syncthreads();
    if (threadIdx.x == 0) {
        unsigned int gen = g_bar_gen;
        if (atomicAdd(&g_bar_cnt, 1u) == NCTA - 1) {
            g_bar_cnt = 0;
            __threadfence();
            g_bar_gen = gen + 1;
        } else {
            while (g_bar_gen == gen) { __nanosleep(64); }
        }
        __threadfence();
    }
    __syncthreads();
}

// =================================================================================
// Kernel A: gx[m][n] = sum_k X[m][k] * W[n][k] + bias[n]
//   X: [65536, 512]  (x viewed as [T*B, I]),  W: [1536, 512],  out -> g_gx
//   128x128 CTA tile, BK=8, 256 threads, 8x8 microtile, f32x2 over N-pairs.
// =================================================================================
__global__ __launch_bounds__(256) void gemm_gx(const float* __restrict__ X,
                                               const float* __restrict__ W,
                                               const float* __restrict__ bias) {
    __shared__ float As[8][128];
    __shared__ float Bs[8][128];
    const int tid = threadIdx.x;
    const int m0 = blockIdx.y * 128;
    const int n0 = blockIdx.x * 128;
    const int tx = tid & 15;        // n-subtile (8 cols)
    const int ty = tid >> 4;        // m-subtile (8 rows)
    const int lrow = tid >> 1;      // 0..127
    const int lk = (tid & 1) * 4;   // 0 or 4

    unsigned long long acc[8][4];
#pragma unroll
    for (int i = 0; i < 8; i++)
#pragma unroll
        for (int jp = 0; jp < 4; jp++) acc[i][jp] = 0ull;

    const float* xg = X + (size_t)(m0 + lrow) * 512 + lk;
    const float* wg = W + (size_t)(n0 + lrow) * 512 + lk;

    for (int k0 = 0; k0 < 512; k0 += 8) {
        float4 av = *(const float4*)(xg + k0);
        float4 bv = *(const float4*)(wg + k0);
        __syncthreads();
        As[lk + 0][lrow] = av.x; As[lk + 1][lrow] = av.y;
        As[lk + 2][lrow] = av.z; As[lk + 3][lrow] = av.w;
        Bs[lk + 0][lrow] = bv.x; Bs[lk + 1][lrow] = bv.y;
        Bs[lk + 2][lrow] = bv.z; Bs[lk + 3][lrow] = bv.w;
        __syncthreads();
#pragma unroll
        for (int kk = 0; kk < 8; kk++) {
            float4 a0 = *(const float4*)&As[kk][ty * 8];
            float4 a1 = *(const float4*)&As[kk][ty * 8 + 4];
            float4 b0 = *(const float4*)&Bs[kk][tx * 8];
            float4 b1 = *(const float4*)&Bs[kk][tx * 8 + 4];
            unsigned long long bp0 = pack2(b0.x, b0.y);
            unsigned long long bp1 = pack2(b0.z, b0.w);
            unsigned long long bp2 = pack2(b1.x, b1.y);
            unsigned long long bp3 = pack2(b1.z, b1.w);
            float a[8] = {a0.x, a0.y, a0.z, a0.w, a1.x, a1.y, a1.z, a1.w};
#pragma unroll
            for (int i = 0; i < 8; i++) {
                unsigned long long ad = dup2(a[i]);
                ffma2(acc[i][0], ad, bp0);
                ffma2(acc[i][1], ad, bp1);
                ffma2(acc[i][2], ad, bp2);
                ffma2(acc[i][3], ad, bp3);
            }
        }
    }

    float bs[8];
#pragma unroll
    for (int c = 0; c < 8; c++) bs[c] = bias[n0 + tx * 8 + c];
#pragma unroll
    for (int i = 0; i < 8; i++) {
        size_t base = (size_t)(m0 + ty * 8 + i) * 1536 + n0 + tx * 8;
        float2 p0 = unpack2(acc[i][0]);
        float2 p1 = unpack2(acc[i][1]);
        float2 p2 = unpack2(acc[i][2]);
        float2 p3 = unpack2(acc[i][3]);
        float4 o0 = make_float4(p0.x + bs[0], p0.y + bs[1], p1.x + bs[2], p1.y + bs[3]);
        float4 o1 = make_float4(p2.x + bs[4], p2.y + bs[5], p3.x + bs[6], p3.y + bs[7]);
        *(float4*)&g_gx[base]     = o0;
        *(float4*)&g_gx[base + 4] = o1;
    }
}

// =================================================================================
// Kernel B: persistent GRU recurrence. 128 CTAs x 256 threads.
//   CTA c owns hidden units j in [4c, 4c+4). Thread (b = tid>>2, jj = tid&3)
//   owns cell (b, 4c+jj): computes gh_r/gh_z/gh_n dots over K=512, gate math,
//   carries h(b,j) in a register, mirrors it into the ping-pong global buffer.
//   W_hh slice (12 rows x 512) lives in SMEM for the whole kernel. h is staged
//   through SMEM in 64-wide K-chunks. One grid barrier per timestep.
// =================================================================================
__global__ __launch_bounds__(256) void gru_rec(const float* __restrict__ whh,
                                               const float* __restrict__ bhh,
                                               const int* __restrict__ lens,
                                               float* __restrict__ out) {
    __shared__ float w_s[12][512];   // rows: gate g (0=r,1=z,2=n) * 4 + unit jj
    __shared__ float h_s[64][68];    // pitch 68 floats: 16B-aligned rows, conflict-free

    const int tid = threadIdx.x;
    const int cta = blockIdx.x;
    const int jj = tid & 3;
    const int b  = tid >> 2;          // 0..63
    const int j  = cta * 4 + jj;      // global hidden unit 0..511

    // Preload this CTA's W_hh slice (persistent for all 1024 steps)
    for (int q = tid; q < 12 * 128; q += 256) {
        int row = q >> 7;             // 0..11
        int kq  = (q & 127) << 2;     // 0..508 step 4
        int g   = row >> 2;
        int u   = row & 3;
        *(float4*)&w_s[row][kq] =
            *(const float4*)&whh[(size_t)(g * 512 + cta * 4 + u) * 512 + kq];
    }

    const float bh_r = bhh[j];
    const float bh_z = bhh[512 + j];
    const float bh_n = bhh[1024 + j];
    const int len_b = lens[b];

    float hreg = 0.f;
    g_h[0][b * 512 + j] = 0.f;        // h0 = 0, re-done every launch (graph replay safe)
    __syncthreads();
    grid_sync();                       // zeros + weights visible everywhere

    for (int t = 0; t < 1024; t++) {
        const float* hc = g_h[t & 1];
        unsigned long long ar0 = 0, ar1 = 0, az0 = 0, az1 = 0, an0 = 0, an1 = 0;

        for (int kc = 0; kc < 512; kc += 64) {
            // stage h chunk [64][64] into SMEM (4 threads per b-row, 16 floats each)
            {
                const float4* src = (const float4*)(hc + b * 512 + kc + jj * 16);
                float4 v0 = src[0], v1 = src[1], v2 = src[2], v3 = src[3];
                float4* dst = (float4*)&h_s[b][jj * 16];
                dst[0] = v0; dst[1] = v1; dst[2] = v2; dst[3] = v3;
            }
            __syncthreads();
#pragma unroll
            for (int kk = 0; kk < 64; kk += 4) {
                ulonglong2 h2 = *(const ulonglong2*)&h_s[b][kk];
                ulonglong2 wr = *(const ulonglong2*)&w_s[jj][kc + kk];
                ulonglong2 wz = *(const ulonglong2*)&w_s[4 + jj][kc + kk];
                ulonglong2 wn = *(const ulonglong2*)&w_s[8 + jj][kc + kk];
                ffma2(ar0, h2.x, wr.x); ffma2(ar1, h2.y, wr.y);
                ffma2(az0, h2.x, wz.x); ffma2(az1, h2.y, wz.y);
                ffma2(an0, h2.x, wn.x); ffma2(an1, h2.y, wn.y);
            }
            __syncthreads();
        }

        float ghr = sum2(ar0) + sum2(ar1) + bh_r;
        float ghz = sum2(az0) + sum2(az1) + bh_z;
        float ghn = sum2(an0) + sum2(an1) + bh_n;

        int gxoff = (t * 64 + b) * 1536 + j;
        float gxr = g_gx[gxoff];
        float gxz = g_gx[gxoff + 512];
        float gxn = g_gx[gxoff + 1024];

        float r = 1.f / (1.f + __expf(-(gxr + ghr)));
        float z = 1.f / (1.f + __expf(-(gxz + ghz)));
        float n = tanhf(gxn + r * ghn);
        float hnew = (1.f - z) * n + z * hreg;

        bool act = (t < len_b);
        out[(size_t)t * 32768 + b * 512 + j] = act ? hnew : 0.f;
        if (act) hreg = hnew;
        g_h[(t + 1) & 1][b * 512 + j] = hreg;

        grid_sync();   // step t writes visible before step t+1 reads
    }

    // h_last: [1, B, H] appended after output
    out[(size_t)1024 * 32768 + b * 512 + j] = hreg;
}

// =================================================================================
// Inputs (metadata order): x[T,B,I] f32, batch_lengths[B] i32, w_ih[3H,I] f32,
// w_hh[3H,H] f32, b_ih[3H] f32, b_hh[3H] f32.
// Output: output[T,B,H] then h_last[1,B,H], fp32.
// =================================================================================
extern "C" void kernel_launch(void* const* d_in, const int* in_sizes, int n_in,
                              void* d_out, int out_size) {
    const float* x   = (const float*)d_in[0];
    const int*   len = (const int*)  d_in[1];
    const float* wih = (const float*)d_in[2];
    const float* whh = (const float*)d_in[3];
    const float* bih = (const float*)d_in[4];
    const float* bhh = (const float*)d_in[5];
    float* out = (float*)d_out;

    (void)in_sizes; (void)n_in; (void)out_size;

    gemm_gx<<<dim3(12, 512), 256>>>(x, wih, bih);
    gru_rec<<<NCTA, 256>>>(whh, bhh, len, out);
}

// round 3
// speedup vs baseline: 3.5025x; 3.5025x over previous
#include <cuda_runtime.h>

// Problem constants: T=1024, B=64, I=512, H=512, 3H=1536
#define NCTA 128   // persistent recurrent kernel grid (<= 148 SMs -> all co-resident)

// ---------------- device-global scratch (no allocation allowed) ----------------
__device__ float g_gx[100663296];                       // [1024*64, 1536] input gate pre-acts
__device__ __align__(16) float g_hT[2][32768];          // ping-pong TRANSPOSED h: [512 units][64 b]
__device__ unsigned int g_bar_cnt = 0;
__device__ volatile unsigned int g_bar_gen = 0;

// ---------------- f32x2 packed-math helpers (Blackwell, PTX-only path) ----------
__device__ __forceinline__ void ffma2(unsigned long long &acc, unsigned long long a,
                                      unsigned long long b) {
    asm("fma.rn.f32x2 %0, %1, %2, %0;" : "+l"(acc) : "l"(a), "l"(b));
}
__device__ __forceinline__ unsigned long long dup2(float a) {
    unsigned long long r; asm("mov.b64 %0, {%1, %1};" : "=l"(r) : "f"(a)); return r;
}
__device__ __forceinline__ unsigned long long pack2(float lo, float hi) {
    unsigned long long r; asm("mov.b64 %0, {%1, %2};" : "=l"(r) : "f"(lo), "f"(hi)); return r;
}
__device__ __forceinline__ float2 unpack2(unsigned long long v) {
    float2 f; asm("mov.b64 {%0, %1}, %2;" : "=f"(f.x), "=f"(f.y) : "l"(v)); return f;
}

// ---------------- software grid barrier (all NCTA CTAs resident) ----------------
// __threadfence() (gpu scope) emits CCTL.IVALL -> flushes L1D, so post-barrier
// LDGs observe other SMs' h writes through L2. Load-bearing for correctness.
__device__ __forceinline__ void grid_sync() {
    __threadfence();
    __syncthreads();
    if (threadIdx.x == 0) {
        unsigned int gen = g_bar_gen;
        if (atomicAdd(&g_bar_cnt, 1u) == NCTA - 1) {
            g_bar_cnt = 0;
            __threadfence();
            g_bar_gen = gen + 1;
        } else {
            while (g_bar_gen == gen) { __nanosleep(32); }
        }
        __threadfence();
    }
    __syncthreads();
}

// =================================================================================
// Kernel A: gx[m][n] = sum_k X[m][k] * W[n][k] + bias[n]
//   X: [65536, 512], W: [1536, 512] -> g_gx. 128x128 tile, BK=8, 8x8 microtile.
// =================================================================================
__global__ __launch_bounds__(256) void gemm_gx(const float* __restrict__ X,
                                               const float* __restrict__ W,
                                               const float* __restrict__ bias) {
    __shared__ __align__(16) float As[8][128];
    __shared__ __align__(16) float Bs[8][128];
    const int tid = threadIdx.x;
    const int m0 = blockIdx.y * 128;
    const int n0 = blockIdx.x * 128;
    const int tx = tid & 15;
    const int ty = tid >> 4;
    const int lrow = tid >> 1;
    const int lk = (tid & 1) * 4;

    unsigned long long acc[8][4];
#pragma unroll
    for (int i = 0; i < 8; i++)
#pragma unroll
        for (int jp = 0; jp < 4; jp++) acc[i][jp] = 0ull;

    const float* xg = X + (size_t)(m0 + lrow) * 512 + lk;
    const float* wg = W + (size_t)(n0 + lrow) * 512 + lk;

    for (int k0 = 0; k0 < 512; k0 += 8) {
        float4 av = *(const float4*)(xg + k0);
        float4 bv = *(const float4*)(wg + k0);
        __syncthreads();
        As[lk + 0][lrow] = av.x; As[lk + 1][lrow] = av.y;
        As[lk + 2][lrow] = av.z; As[lk + 3][lrow] = av.w;
        Bs[lk + 0][lrow] = bv.x; Bs[lk + 1][lrow] = bv.y;
        Bs[lk + 2][lrow] = bv.z; Bs[lk + 3][lrow] = bv.w;
        __syncthreads();
#pragma unroll
        for (int kk = 0; kk < 8; kk++) {
            float4 a0 = *(const float4*)&As[kk][ty * 8];
            float4 a1 = *(const float4*)&As[kk][ty * 8 + 4];
            float4 b0 = *(const float4*)&Bs[kk][tx * 8];
            float4 b1 = *(const float4*)&Bs[kk][tx * 8 + 4];
            unsigned long long bp0 = pack2(b0.x, b0.y);
            unsigned long long bp1 = pack2(b0.z, b0.w);
            unsigned long long bp2 = pack2(b1.x, b1.y);
            unsigned long long bp3 = pack2(b1.z, b1.w);
            float a[8] = {a0.x, a0.y, a0.z, a0.w, a1.x, a1.y, a1.z, a1.w};
#pragma unroll
            for (int i = 0; i < 8; i++) {
                unsigned long long ad = dup2(a[i]);
                ffma2(acc[i][0], ad, bp0);
                ffma2(acc[i][1], ad, bp1);
                ffma2(acc[i][2], ad, bp2);
                ffma2(acc[i][3], ad, bp3);
            }
        }
    }

    float bs[8];
#pragma unroll
    for (int c = 0; c < 8; c++) bs[c] = bias[n0 + tx * 8 + c];
#pragma unroll
    for (int i = 0; i < 8; i++) {
        size_t base = (size_t)(m0 + ty * 8 + i) * 1536 + n0 + tx * 8;
        float2 p0 = unpack2(acc[i][0]);
        float2 p1 = unpack2(acc[i][1]);
        float2 p2 = unpack2(acc[i][2]);
        float2 p3 = unpack2(acc[i][3]);
        float4 o0 = make_float4(p0.x + bs[0], p0.y + bs[1], p1.x + bs[2], p1.y + bs[3]);
        float4 o1 = make_float4(p2.x + bs[4], p2.y + bs[5], p3.x + bs[6], p3.y + bs[7]);
        *(float4*)&g_gx[base]     = o0;
        *(float4*)&g_gx[base + 4] = o1;
    }
}

// =================================================================================
// Kernel B: persistent GRU recurrence, FMA-bound layout.
//   128 CTAs x 256 threads. CTA owns 4 hidden units (12 gate-rows r/z/n x 4).
//   K=512 split across 8 warps (64 each). Lane owns b-pair (2l, 2l+1) x all 12 rows:
//   per k: 1 coalesced LDG.64 of h-pair (transposed layout) + broadcast w from SMEM
//   -> 12 FFMA2. Cross-warp K-reduction via 24KB SMEM, then gate math.
// =================================================================================
__global__ __launch_bounds__(256) void gru_rec(const float* __restrict__ whh,
                                               const float* __restrict__ bhh,
                                               const int* __restrict__ lens,
                                               float* __restrict__ out) {
    __shared__ __align__(16) float w_s[12][512];    // 24KB: row = gate*4 + unit
    __shared__ __align__(16) float red[8][64][12];  // 24KB: [warp][b][row] partials

    const int tid  = threadIdx.x;
    const int cta  = blockIdx.x;
    const int warp = tid >> 5;
    const int lane = tid & 31;
    const int gb = tid >> 2;          // gate-phase batch 0..63
    const int gu = tid & 3;           // gate-phase unit-in-CTA 0..3
    const int j  = cta * 4 + gu;      // global unit

    // Preload W_hh slice (persistent across all 1024 steps)
    for (int q = tid; q < 12 * 128; q += 256) {
        int row = q >> 7;
        int kq  = (q & 127) << 2;
        int g   = row >> 2;
        int u   = row & 3;
        *(float4*)&w_s[row][kq] =
            *(const float4*)&whh[(size_t)(g * 512 + cta * 4 + u) * 512 + kq];
    }

    const float bh_r = bhh[j];
    const float bh_z = bhh[512 + j];
    const float bh_n = bhh[1024 + j];
    const int len_b = lens[gb];

    float hreg = 0.f;
    g_hT[0][j * 64 + gb] = 0.f;       // h0 = 0 (re-done every launch: graph-replay safe)
    __syncthreads();
    grid_sync();

    const int ks = warp * 64;         // this warp's K slice

    for (int t = 0; t < 1024; t++) {
        // Prefetch input-side gates early (latency hidden behind the k-loop)
        const float* gxp = g_gx + (size_t)(t * 64 + gb) * 1536 + j;
        float gxr = gxp[0];
        float gxz = gxp[512];
        float gxn = gxp[1024];

        const float* hc = g_hT[t & 1] + (size_t)ks * 64 + 2 * lane;

        unsigned long long acc[12];
#pragma unroll
        for (int r = 0; r < 12; r++) acc[r] = 0ull;

#pragma unroll 4
        for (int kq = 0; kq < 16; kq++) {
            // 4 coalesced h b-pair loads (h_T[k][b]: 8B per lane, contiguous across warp)
            unsigned long long h0 = *(const unsigned long long*)(hc + (kq * 4 + 0) * 64);
            unsigned long long h1 = *(const unsigned long long*)(hc + (kq * 4 + 1) * 64);
            unsigned long long h2 = *(const unsigned long long*)(hc + (kq * 4 + 2) * 64);
            unsigned long long h3 = *(const unsigned long long*)(hc + (kq * 4 + 3) * 64);
#pragma unroll
            for (int r = 0; r < 12; r++) {
                float4 wv = *(const float4*)&w_s[r][ks + kq * 4];  // broadcast LDS.128
                ffma2(acc[r], h0, dup2(wv.x));
                ffma2(acc[r], h1, dup2(wv.y));
                ffma2(acc[r], h2, dup2(wv.z));
                ffma2(acc[r], h3, dup2(wv.w));
            }
        }

        // Fold b-pair partials into SMEM: red[warp][b][row]
        const int b0 = 2 * lane;
#pragma unroll
        for (int r = 0; r < 12; r++) {
            float2 p = unpack2(acc[r]);
            red[warp][b0][r]     = p.x;
            red[warp][b0 + 1][r] = p.y;
        }
        __syncthreads();

        // Gate phase: reduce 8 warp partials, apply GRU cell
        float ghr = bh_r, ghz = bh_z, ghn = bh_n;
#pragma unroll
        for (int w = 0; w < 8; w++) {
            ghr += red[w][gb][gu];
            ghz += red[w][gb][4 + gu];
            ghn += red[w][gb][8 + gu];
        }

        float r = 1.f / (1.f + __expf(-(gxr + ghr)));
        float z = 1.f / (1.f + __expf(-(gxz + ghz)));
        float n = tanhf(gxn + r * ghn);
        float hnew = (1.f - z) * n + z * hreg;

        bool act = (t < len_b);
        out[(size_t)t * 32768 + gb * 512 + j] = act ? hnew : 0.f;
        if (act) hreg = hnew;
        g_hT[(t + 1) & 1][j * 64 + gb] = hreg;   // transposed write, coalesced-ish

        grid_sync();   // h writes visible (incl. L1 flush) before next step reads
    }

    // h_last: [1, B, H] appended after output
    out[(size_t)1024 * 32768 + gb * 512 + j] = hreg;
}

// =================================================================================
// Inputs (metadata order): x[T,B,I] f32, batch_lengths[B] i32, w_ih[3H,I] f32,
// w_hh[3H,H] f32, b_ih[3H] f32, b_hh[3H] f32.  Output: [T,B,H] then [1,B,H], fp32.
// =================================================================================
extern "C" void kernel_launch(void* const* d_in, const int* in_sizes, int n_in,
                              void* d_out, int out_size) {
    const float* x   = (const float*)d_in[0];
    const int*   len = (const int*)  d_in[1];
    const float* wih = (const float*)d_in[2];
    const float* whh = (const float*)d_in[3];
    const float* bih = (const float*)d_in[4];
    const float* bhh = (const float*)d_in[5];
    float* out = (float*)d_out;

    (void)in_sizes; (void)n_in; (void)out_size;

    gemm_gx<<<dim3(12, 512), 256>>>(x, wih, bih);
    gru_rec<<<NCTA, 256>>>(whh, bhh, len, out);
}